// round 15
// baseline (speedup 1.0000x reference)
#include <cuda_runtime.h>
#include <cuda_fp16.h>
#include <cstdint>

#define Hh 256
#define Ww 256
#define Bb 8
#define HW 65536
#define NPIX (Bb*HW)   // 524288

// Scratch (device globals — no allocation allowed)
__device__ float    g_bufA[(size_t)Bb*128*HW];
__device__ float    g_bufB[(size_t)Bb*128*HW];
__device__ uint32_t g_bufP[(size_t)Bb*64*HW];    // packed fp16 x (2 ci per word)
__device__ float    g_maskA[(size_t)Bb*HW];
__device__ float    g_maskB[(size_t)Bb*HW];
__device__ float    g_sums[512];                 // two ping-pong buffers of 256
__device__ uint2    g_wsplit[100000];            // fp16 (hi,lo) weight pair words

// ---------------------------------------------------------------------------
// helpers
// ---------------------------------------------------------------------------
__device__ __forceinline__ uint32_t pack2_f16(float a, float b) {
    __half2 h = __floats2half2_rn(a, b);
    return *reinterpret_cast<uint32_t*>(&h);
}
__device__ __forceinline__ void mma16f(float* c,
                                       uint32_t a0, uint32_t a1, uint32_t a2, uint32_t a3,
                                       uint32_t b0, uint32_t b1) {
    asm volatile(
        "mma.sync.aligned.m16n8k16.row.col.f32.f16.f16.f32 "
        "{%0,%1,%2,%3},{%4,%5,%6,%7},{%8,%9},{%0,%1,%2,%3};"
        : "+f"(c[0]), "+f"(c[1]), "+f"(c[2]), "+f"(c[3])
        : "r"(a0), "r"(a1), "r"(a2), "r"(a3), "r"(b0), "r"(b1));
}
__device__ __forceinline__ void cp_async16(uint32_t dst_smem, const void* src, int src_size) {
    asm volatile("cp.async.cg.shared.global [%0],[%1],16,%2;\n"
                 :: "r"(dst_smem), "l"(src), "r"(src_size));
}
__device__ __forceinline__ uint2 wpair(float v0, float v1) {
    __half h0 = __float2half_rn(v0), h1 = __float2half_rn(v1);
    __half l0 = __float2half_rn(v0 - __half2float(h0));
    __half l1 = __float2half_rn(v1 - __half2float(h1));
    __half2 HH = __halves2half2(h0, h1), LL = __halves2half2(l0, l1);
    return make_uint2(*reinterpret_cast<uint32_t*>(&HH), *reinterpret_cast<uint32_t*>(&LL));
}

// ---------------------------------------------------------------------------
// Weight pre-split, ALL 3x3 layers in one launch.
// ---------------------------------------------------------------------------
__device__ __forceinline__ void presplit_one(const float* W, uint2* dst,
                                             int CIN, int CO_BLK, int i)
{
    int co   = i % CO_BLK;
    int pr   = (i / CO_BLK) & 7;
    int t    = (i / (CO_BLK*8)) % 9;
    int rest = i / (CO_BLK*72);
    int chunks = CIN >> 4;
    int q = rest % chunks;
    int s = rest / chunks;
    int ci = q*16 + 2*pr;
    const float* wb = W + ((size_t)(s*CO_BLK + co)*CIN + ci)*9 + t;
    dst[i] = wpair(wb[0], wb[9]);
}
__global__ void presplit3x3_all(const float* __restrict__ W0, const float* __restrict__ W1,
                                const float* __restrict__ W2, const float* __restrict__ W3,
                                const float* __restrict__ W4, uint2* __restrict__ dst)
{
    int j = blockIdx.x*256 + threadIdx.x;
    if (j >= 69120) return;
    if      (j < 2304)  presplit_one(W0, dst,          32, 16,  j);
    else if (j < 4608)  presplit_one(W1, dst + 2304,   16, 32,  j - 2304);
    else if (j < 13824) presplit_one(W2, dst + 4608,   32, 64,  j - 4608);
    else if (j < 32256) presplit_one(W3, dst + 13824,  64, 64,  j - 13824);
    else                presplit_one(W4, dst + 32256,  64, 128, j - 32256);
}
__global__ void presplit1x1_kernel(const float* __restrict__ W, uint2* __restrict__ dst)
{
    int i = blockIdx.x*256 + threadIdx.x;
    if (i >= 4096) return;
    int co = i & 63, pr = (i >> 6) & 7, q = i >> 9;
    int ci = q*16 + 2*pr;
    dst[i] = wpair(W[co*128 + ci], W[co*128 + ci + 1]);
}

// ---------------------------------------------------------------------------
// Activation transform + fused BN-stats finalization + next-sums zeroing.
// ---------------------------------------------------------------------------
template<bool BN, bool MASKED>
__global__ void transform_kernel(const float* __restrict__ y,
                                 const float* __restrict__ m,
                                 const float* __restrict__ sums,
                                 const float* __restrict__ gam,
                                 const float* __restrict__ bet,
                                 float* __restrict__ sums_next,
                                 uint32_t* __restrict__ out, int C, int n4)
{
    __shared__ float ssm[256];
    const int tid = threadIdx.x;
    if (BN) {
        if (tid < C) {
            const float invN = 1.f / (float)NPIX;
            float mean = sums[tid] * invN;
            float var  = sums[C + tid] * invN - mean*mean;
            float sc = gam[tid] * rsqrtf(var + 1e-5f);
            ssm[tid]     = sc;
            ssm[C + tid] = fmaf(-mean, sc, bet[tid]);
        }
        __syncthreads();
    }
    if (blockIdx.x == 0 && sums_next != nullptr && tid < 256) sums_next[tid] = 0.f;

    int i = blockIdx.x*256 + tid;
    if (i >= n4) return;
    int plane = i >> 14;
    int half = C >> 1;
    int pp = plane % half;
    int b  = plane / half;
    int c0 = pp*2;
    float sc0 = 1.f, sh0 = 0.f, sc1 = 1.f, sh1 = 0.f;
    if (BN) { sc0 = ssm[c0]; sh0 = ssm[C + c0]; sc1 = ssm[c0+1]; sh1 = ssm[C + c0 + 1]; }
    int px4 = i & 16383;
    float4 v0 = ((const float4*)y)[(((size_t)b*C + c0    ) << 14) + px4];
    float4 v1 = ((const float4*)y)[(((size_t)b*C + c0 + 1) << 14) + px4];
    float4 mk = make_float4(1.f,1.f,1.f,1.f);
    if (MASKED) mk = ((const float4*)m)[(((size_t)b) << 14) + px4];
    const float* p0 = &v0.x; const float* p1 = &v1.x; const float* pm = &mk.x;
    uint32_t r[4];
    #pragma unroll
    for (int k = 0; k < 4; k++) {
        float a = p0[k], c = p1[k];
        if (BN) {
            a = fmaf(a, sc0, sh0); a = a >= 0.f ? a : 0.01f*a;
            c = fmaf(c, sc1, sh1); c = c >= 0.f ? c : 0.01f*c;
        }
        if (MASKED) { a *= pm[k]; c *= pm[k]; }
        r[k] = pack2_f16(a, c);
    }
    ((uint4*)out)[i] = make_uint4(r[0], r[1], r[2], r[3]);
}

// ---------------------------------------------------------------------------
// Fused sparse-conv block, fp16 asymmetric-split MMA, NBUF-buffered 16B
// cp.async staging, conflict-free smem stride (3*WPX ≡ 8 mod 32).
// ---------------------------------------------------------------------------
template<int CIN, int CO_BLK, int NSPLIT, int DIL, int PXT, int WARPS, int NBUF, int MINB>
__global__ void __launch_bounds__(WARPS*32, MINB) conv_mma_kernel(
    const uint32_t* __restrict__ xpk, const float* __restrict__ min_,
    const uint2* __restrict__ wsplit, const float* __restrict__ bg,
    float* __restrict__ yout, float* __restrict__ mout,
    float* __restrict__ sums)
{
    constexpr int NT    = WARPS*32;
    constexpr int PXG   = WARPS*16/CO_BLK;
    constexpr int XW    = PXT + 2*DIL;          // mask window (start x0-DIL)
    constexpr int WPX   = ((PXT + 8 - 24 + 31)/32)*32 + 24;
    constexpr int NCH   = (PXT + 8) / 4;        // 16B chunks per x row
    constexpr int XTSZ  = 24*WPX;
    constexpr int COUTT = CO_BLK*NSPLIT;
    constexpr int TX    = 256/PXT;
    constexpr int CHUNKS = CIN/16;
    constexpr int PLANES = CIN/2;

    extern __shared__ char dsm[];
    uint32_t* xt  = (uint32_t*)dsm;             // [NBUF][24][WPX], window start x0-4
    float*  msk = (float*)(xt + NBUF*XTSZ);     // [3][WPX]
    float*  invc= msk + 3*WPX;                  // [PXT]
    float*  red = invc + PXT;                   // [2*CO_BLK]

    const int tid  = threadIdx.x;
    const int lane = tid & 31, warp = tid >> 5;
    const int g    = lane >> 2, tig = lane & 3;
    const int cog  = warp / PXG, pxg = warp % PXG;
    const int pxb  = pxg * 64;
    const int cb   = cog * 16;
    const uint32_t sx = (uint32_t)__cvta_generic_to_shared(xt);

    const int tile = blockIdx.x;
    const int x0 = (tile % TX) * PXT;
    const int y0 = tile / TX;
    const int z  = blockIdx.z;
    const int b  = z / NSPLIT;
    const int split = z % NSPLIT;
    const int co_base = split * CO_BLK;

    // --- stage mask rows ---
    for (int i = tid; i < 3*XW; i += NT) {
        int col = i % XW, r = i / XW;
        int gy = y0 + (r-1)*DIL, gx = x0 - DIL + col;
        float v = 0.f;
        if (gy >= 0 && gy < Hh && gx >= 0 && gx < Ww) v = min_[b*HW + gy*Ww + gx];
        msk[r*WPX + col] = v;
    }
    for (int i = tid; i < 2*CO_BLK; i += NT) red[i] = 0.f;

    // 16B vector staging: chunk ch covers gx = x0-4+4ch .. +3 (all-or-nothing OOB)
    auto stage = [&](int q, int buf) {
        for (int pr = warp; pr < 8; pr += WARPS) {
            const uint32_t* srcp = xpk + (size_t)(b*PLANES + q*8 + pr)*HW;
            #pragma unroll
            for (int r = 0; r < 3; r++) {
                int gy = y0 + (r-1)*DIL;
                bool rowok = ((unsigned)gy < (unsigned)Hh);
                const uint32_t* srow = srcp + (rowok ? gy*Ww : 0);
                uint32_t dstb = sx + ((buf*XTSZ + (pr*3 + r)*WPX) << 2);
                #pragma unroll
                for (int ch = lane; ch < NCH; ch += 32) {
                    int gx = x0 - 4 + ch*4;
                    bool ok = rowok && (gx >= 0) && (gx < Ww);
                    cp_async16(dstb + (ch << 4), srow + (ok ? gx : 0), ok ? 16 : 0);
                }
            }
        }
        asm volatile("cp.async.commit_group;\n");
    };

    stage(0, 0);
    __syncthreads();

    // --- per-pixel 1/count + mask maxpool (overlaps chunk-0 arrival) ---
    for (int px = tid; px < PXT; px += NT) {
        float cnt = 0.f, mn = 0.f;
        #pragma unroll
        for (int ky = 0; ky < 3; ky++)
            #pragma unroll
            for (int kx = 0; kx < 3; kx++) {
                float v = msk[ky*WPX + px + kx*DIL];
                cnt += v; mn = fmaxf(mn, v);
            }
        invc[px] = 1.f / fmaxf(cnt * (float)CIN, 1e-5f);
        if (split == 0) mout[b*HW + y0*Ww + x0 + px] = mn;
    }

    float c[8][4];
    #pragma unroll
    for (int f = 0; f < 8; f++) { c[f][0]=0.f; c[f][1]=0.f; c[f][2]=0.f; c[f][3]=0.f; }

    for (int q = 0; q < CHUNKS; q++) {
        const int buf = (NBUF == 1) ? 0 : (q & 1);
        if (NBUF == 2 && q + 1 < CHUNKS) {
            stage(q + 1, buf ^ 1);
            asm volatile("cp.async.wait_group 1;\n");
        } else {
            asm volatile("cp.async.wait_group 0;\n");
        }
        __syncthreads();

        const uint32_t* xb = xt + buf*XTSZ;
        const uint2* Ab = wsplit + (size_t)(split*CHUNKS + q)*72*CO_BLK + cb + g;
        #pragma unroll 9
        for (int t = 0; t < 9; t++) {
            const int ky = t/3, kx = t - 3*ky;
            const int xoff = (kx-1)*DIL + 4;        // window-start shift
            const uint2* Ap = Ab + t*8*CO_BLK;
            uint2 A0 = __ldg(Ap + tig*CO_BLK);
            uint2 A1 = __ldg(Ap + tig*CO_BLK + 8);
            uint2 A2 = __ldg(Ap + (tig+4)*CO_BLK);
            uint2 A3 = __ldg(Ap + (tig+4)*CO_BLK + 8);
            const uint32_t* brow0 = &xb[(tig    *3 + ky)*WPX + pxb + xoff + g];
            const uint32_t* brow1 = &xb[((tig+4)*3 + ky)*WPX + pxb + xoff + g];
            #pragma unroll
            for (int f = 0; f < 8; f++) {
                uint32_t b0 = brow0[f*8];
                uint32_t b1 = brow1[f*8];
                mma16f(c[f], A0.x, A1.x, A2.x, A3.x, b0, b1);  // w_hi * x
                mma16f(c[f], A0.y, A1.y, A2.y, A3.y, b0, b1);  // w_lo * x
            }
        }
        if (q + 1 < CHUNKS) {
            __syncthreads();                        // all reads of buf done
            if (NBUF == 1) stage(q + 1, 0);         // restage in place
        }
    }

    // --- epilogue ---
    const int gco0 = co_base + cb + g;
    const int gco1 = gco0 + 8;
    const float b0v = bg[gco0], b1v = bg[gco1];
    float* rowp0 = yout + (size_t)(b*COUTT + gco0)*HW + y0*Ww + x0;
    float* rowp1 = yout + (size_t)(b*COUTT + gco1)*HW + y0*Ww + x0;
    float s0 = 0.f, q0 = 0.f, s1 = 0.f, q1 = 0.f;
    #pragma unroll
    for (int f = 0; f < 8; f++) {
        int pxl = pxb + f*8 + 2*tig;
        float i0 = invc[pxl], i1 = invc[pxl + 1];
        float y00 = fmaf(c[f][0], i0, b0v);
        float y01 = fmaf(c[f][1], i1, b0v);
        float y10 = fmaf(c[f][2], i0, b1v);
        float y11 = fmaf(c[f][3], i1, b1v);
        *(float2*)(rowp0 + pxl) = make_float2(y00, y01);
        *(float2*)(rowp1 + pxl) = make_float2(y10, y11);
        s0 += y00 + y01; q0 += y00*y00 + y01*y01;
        s1 += y10 + y11; q1 += y10*y10 + y11*y11;
    }
    #pragma unroll
    for (int o = 1; o <= 2; o <<= 1) {
        s0 += __shfl_xor_sync(0xffffffffu, s0, o);
        q0 += __shfl_xor_sync(0xffffffffu, q0, o);
        s1 += __shfl_xor_sync(0xffffffffu, s1, o);
        q1 += __shfl_xor_sync(0xffffffffu, q1, o);
    }
    if (tig == 0) {
        atomicAdd(&red[cb + g],              s0);
        atomicAdd(&red[CO_BLK + cb + g],     q0);
        atomicAdd(&red[cb + g + 8],          s1);
        atomicAdd(&red[CO_BLK + cb + g + 8], q1);
    }
    __syncthreads();
    if (tid < CO_BLK) {
        atomicAdd(&sums[co_base + tid],          red[tid]);
        atomicAdd(&sums[COUTT + co_base + tid],  red[CO_BLK + tid]);
    }
}

// ---------------------------------------------------------------------------
// final 1x1 conv 128 -> 64, fp16 asymmetric split, 16B double-buffered staging
// ---------------------------------------------------------------------------
__global__ void __launch_bounds__(256, 3) conv1x1_mma_kernel(
    const uint32_t* __restrict__ xpk, const uint2* __restrict__ wsp1,
    const float* __restrict__ bg, float* __restrict__ out)
{
    constexpr int CO = 64, PXT = 128, WPX1 = 140, PLANES = 64;
    __shared__ uint32_t xt[2*8*WPX1];

    const int tid = threadIdx.x, lane = tid & 31, warp = tid >> 5;
    const int g = lane >> 2, tig = lane & 3;
    const int cog = warp >> 1, pxg = warp & 1;
    const int pxb = pxg * 64;
    const int tile = blockIdx.x;
    const int x0 = (tile & 1)*PXT, y0 = tile >> 1;
    const int b  = blockIdx.z;
    const uint32_t sx = (uint32_t)__cvta_generic_to_shared(xt);

    auto stage = [&](int q, int buf) {
        const int pr = warp;
        const uint32_t* s = xpk + (size_t)(b*PLANES + q*8 + pr)*HW + y0*Ww + x0;
        uint32_t dstb = sx + ((buf*8*WPX1 + pr*WPX1) << 2);
        cp_async16(dstb + (lane << 4), s + lane*4, 16);
        asm volatile("cp.async.commit_group;\n");
    };

    float c[8][4];
    #pragma unroll
    for (int f = 0; f < 8; f++) { c[f][0]=0.f; c[f][1]=0.f; c[f][2]=0.f; c[f][3]=0.f; }

    stage(0, 0);
    for (int q = 0; q < 8; q++) {
        const int buf = q & 1;
        if (q + 1 < 8) {
            stage(q + 1, buf ^ 1);
            asm volatile("cp.async.wait_group 1;\n");
        } else {
            asm volatile("cp.async.wait_group 0;\n");
        }
        __syncthreads();

        const uint32_t* xb = xt + buf*8*WPX1;
        const uint2* Ap = wsp1 + q*512;
        uint2 a0 = __ldg(Ap + tig*64 + cog*16 + g);
        uint2 a1 = __ldg(Ap + tig*64 + cog*16 + g + 8);
        uint2 a2 = __ldg(Ap + (tig+4)*64 + cog*16 + g);
        uint2 a3 = __ldg(Ap + (tig+4)*64 + cog*16 + g + 8);
        #pragma unroll
        for (int f = 0; f < 8; f++) {
            uint32_t b0 = xb[tig    *WPX1 + pxb + f*8 + g];
            uint32_t b1 = xb[(tig+4)*WPX1 + pxb + f*8 + g];
            mma16f(c[f], a0.x, a1.x, a2.x, a3.x, b0, b1);
            mma16f(c[f], a0.y, a1.y, a2.y, a3.y, b0, b1);
        }
        __syncthreads();
    }
    const int co0 = cog*16 + g, co1 = co0 + 8;
    const float b0v = bg[co0], b1v = bg[co1];
    float* r0 = out + (size_t)(b*CO + co0)*HW + y0*Ww + x0;
    float* r1 = out + (size_t)(b*CO + co1)*HW + y0*Ww + x0;
    #pragma unroll
    for (int f = 0; f < 8; f++) {
        int pxl = pxb + f*8 + 2*tig;
        *(float2*)(r0 + pxl) = make_float2(c[f][0] + b0v, c[f][1] + b0v);
        *(float2*)(r1 + pxl) = make_float2(c[f][2] + b1v, c[f][3] + b1v);
    }
}

// ---------------------------------------------------------------------------
extern "C" void kernel_launch(void* const* d_in, const int* in_sizes, int n_in,
                              void* d_out, int out_size)
{
    const float* feat = (const float*)d_in[0];
    const float* mask = (const float*)d_in[1];
    const float* Wl[5]; const float* bl[5]; const float* gl[5]; const float* bel[5];
    for (int l = 0; l < 5; l++) {
        Wl[l]  = (const float*)d_in[2 + 4*l];
        bl[l]  = (const float*)d_in[3 + 4*l];
        gl[l]  = (const float*)d_in[4 + 4*l];
        bel[l] = (const float*)d_in[5 + 4*l];
    }
    const float* Wf = (const float*)d_in[22];
    const float* bf = (const float*)d_in[23];

    float *bufA, *bufB, *mA, *mB, *sumsG;
    uint32_t* P;
    uint2* wsp;
    cudaGetSymbolAddress((void**)&bufA, g_bufA);
    cudaGetSymbolAddress((void**)&bufB, g_bufB);
    cudaGetSymbolAddress((void**)&P,    g_bufP);
    cudaGetSymbolAddress((void**)&mA,   g_maskA);
    cudaGetSymbolAddress((void**)&mB,   g_maskB);
    cudaGetSymbolAddress((void**)&sumsG, g_sums);
    cudaGetSymbolAddress((void**)&wsp,  g_wsplit);
    float* su0 = sumsG;
    float* su1 = sumsG + 256;

    const int off0 = 0, off1 = 2304, off2 = 4608, off3 = 13824, off4 = 32256;
    const int off1x1 = 69120;
    presplit3x3_all<<<270, 256>>>(Wl[0], Wl[1], Wl[2], Wl[3], Wl[4], wsp);
    presplit1x1_kernel<<<16, 256>>>(Wf, wsp+off1x1);

    // WPX: 256->280, 128->152, 64->88 ; L0/L1 single-buffered now
    const int smem_L0 = 1*24*280*4 + 3*280*4 + 256*4 + 2*16*4 + 16;   // 31408
    const int smem_L1 = 1*24*280*4 + 3*280*4 + 256*4 + 2*32*4 + 16;   // 31536
    const int smem_Lx = 2*24*152*4 + 3*152*4 + 128*4 + 2*64*4 + 16;   // 32048
    const int smem_L4 = 2*24*88*4  + 3*88*4  + 64*4  + 2*128*4 + 16;  // 19248

    auto k0 = conv_mma_kernel<32,16,1,1,256,4,1,4>;
    auto k1 = conv_mma_kernel<16,32,1,2,256,8,1,3>;
    auto k2 = conv_mma_kernel<32,64,1,1,128,8,2,3>;
    auto k3 = conv_mma_kernel<64,64,1,2,128,8,2,3>;
    auto k4 = conv_mma_kernel<64,128,1,1,64,8,2,3>;
    cudaFuncSetAttribute(k0, cudaFuncAttributeMaxDynamicSharedMemorySize, smem_L0);
    cudaFuncSetAttribute(k1, cudaFuncAttributeMaxDynamicSharedMemorySize, smem_L1);
    cudaFuncSetAttribute(k2, cudaFuncAttributeMaxDynamicSharedMemorySize, smem_Lx);
    cudaFuncSetAttribute(k3, cudaFuncAttributeMaxDynamicSharedMemorySize, smem_Lx);
    cudaFuncSetAttribute(k4, cudaFuncAttributeMaxDynamicSharedMemorySize, smem_L4);

    auto TFM  = transform_kernel<true,  true >;
    auto TF0  = transform_kernel<false, true >;
    auto TFNM = transform_kernel<true,  false>;
    #define TGRID(C) ((C)*256)

    // input transform: feat*mask -> packed; zeroes su0 for L0
    TF0<<<TGRID(32), 256>>>(feat, mask, nullptr, nullptr, nullptr, su0, P, 32, 32*65536);

    // L0: 32 -> 16, d=1
    k0<<<dim3(256,1,8), 128, smem_L0>>>(P, mask, wsp+off0, bl[0], bufA, mA, su0);
    TFM<<<TGRID(16), 256>>>(bufA, mA, su0, gl[0], bel[0], su1, P, 16, 16*65536);

    // L1: 16 -> 32, d=2
    k1<<<dim3(256,1,8), 256, smem_L1>>>(P, mA, wsp+off1, bl[1], bufB, mB, su1);
    TFM<<<TGRID(32), 256>>>(bufB, mB, su1, gl[1], bel[1], su0, P, 32, 32*65536);

    // L2: 32 -> 64, d=1
    k2<<<dim3(512,1,8), 256, smem_Lx>>>(P, mB, wsp+off2, bl[2], bufA, mA, su0);
    TFM<<<TGRID(64), 256>>>(bufA, mA, su0, gl[2], bel[2], su1, P, 64, 64*65536);

    // L3: 64 -> 64, d=2
    k3<<<dim3(512,1,8), 256, smem_Lx>>>(P, mA, wsp+off3, bl[3], bufB, mB, su1);
    TFM<<<TGRID(64), 256>>>(bufB, mB, su1, gl[3], bel[3], su0, P, 64, 64*65536);

    // L4: 64 -> 128, d=1, single pass
    k4<<<dim3(1024,1,8), 256, smem_L4>>>(P, mB, wsp+off4, bl[4], bufA, mA, su0);
    TFNM<<<TGRID(128), 256>>>(bufA, nullptr, su0, gl[4], bel[4], nullptr, P, 128, 128*65536);

    // final 1x1 conv
    conv1x1_mma_kernel<<<dim3(512,1,8), 256>>>(P, wsp+off1x1, bf, (float*)d_out);

    // final mask
    const int xelems = Bb*64*HW;
    const int melems = Bb*HW;
    if (out_size >= xelems + melems) {
        cudaMemcpyAsync((float*)d_out + xelems, mA, (size_t)melems*sizeof(float),
                        cudaMemcpyDeviceToDevice);
    }
}

// round 16
// speedup vs baseline: 1.0070x; 1.0070x over previous
#include <cuda_runtime.h>
#include <cuda_fp16.h>
#include <cstdint>

#define Hh 256
#define Ww 256
#define Bb 8
#define HW 65536
#define NPIX (Bb*HW)   // 524288

// Scratch (device globals — no allocation allowed)
__device__ float    g_bufA[(size_t)Bb*128*HW];
__device__ float    g_bufB[(size_t)Bb*128*HW];
__device__ uint32_t g_bufP[(size_t)Bb*64*HW];    // packed fp16 x (2 ci per word)
__device__ float    g_maskA[(size_t)Bb*HW];
__device__ float    g_maskB[(size_t)Bb*HW];
__device__ float    g_sums[512];                 // two ping-pong buffers of 256
__device__ uint2    g_wsplit[100000];            // fp16 (hi,lo) weight pair words

// ---------------------------------------------------------------------------
// helpers
// ---------------------------------------------------------------------------
__device__ __forceinline__ uint32_t pack2_f16(float a, float b) {
    __half2 h = __floats2half2_rn(a, b);
    return *reinterpret_cast<uint32_t*>(&h);
}
__device__ __forceinline__ void mma16f(float* c,
                                       uint32_t a0, uint32_t a1, uint32_t a2, uint32_t a3,
                                       uint32_t b0, uint32_t b1) {
    asm volatile(
        "mma.sync.aligned.m16n8k16.row.col.f32.f16.f16.f32 "
        "{%0,%1,%2,%3},{%4,%5,%6,%7},{%8,%9},{%0,%1,%2,%3};"
        : "+f"(c[0]), "+f"(c[1]), "+f"(c[2]), "+f"(c[3])
        : "r"(a0), "r"(a1), "r"(a2), "r"(a3), "r"(b0), "r"(b1));
}
__device__ __forceinline__ void cp_async16(uint32_t dst_smem, const void* src, int src_size) {
    asm volatile("cp.async.cg.shared.global [%0],[%1],16,%2;\n"
                 :: "r"(dst_smem), "l"(src), "r"(src_size));
}
__device__ __forceinline__ uint2 wpair(float v0, float v1) {
    __half h0 = __float2half_rn(v0), h1 = __float2half_rn(v1);
    __half l0 = __float2half_rn(v0 - __half2float(h0));
    __half l1 = __float2half_rn(v1 - __half2float(h1));
    __half2 HH = __halves2half2(h0, h1), LL = __halves2half2(l0, l1);
    return make_uint2(*reinterpret_cast<uint32_t*>(&HH), *reinterpret_cast<uint32_t*>(&LL));
}

// ---------------------------------------------------------------------------
// Weight pre-split, ALL 3x3 layers in one launch.
// ---------------------------------------------------------------------------
__device__ __forceinline__ void presplit_one(const float* W, uint2* dst,
                                             int CIN, int CO_BLK, int i)
{
    int co   = i % CO_BLK;
    int pr   = (i / CO_BLK) & 7;
    int t    = (i / (CO_BLK*8)) % 9;
    int rest = i / (CO_BLK*72);
    int chunks = CIN >> 4;
    int q = rest % chunks;
    int s = rest / chunks;
    int ci = q*16 + 2*pr;
    const float* wb = W + ((size_t)(s*CO_BLK + co)*CIN + ci)*9 + t;
    dst[i] = wpair(wb[0], wb[9]);
}
__global__ void presplit3x3_all(const float* __restrict__ W0, const float* __restrict__ W1,
                                const float* __restrict__ W2, const float* __restrict__ W3,
                                const float* __restrict__ W4, uint2* __restrict__ dst)
{
    int j = blockIdx.x*256 + threadIdx.x;
    if (j >= 69120) return;
    if      (j < 2304)  presplit_one(W0, dst,          32, 16,  j);
    else if (j < 4608)  presplit_one(W1, dst + 2304,   16, 32,  j - 2304);
    else if (j < 13824) presplit_one(W2, dst + 4608,   32, 64,  j - 4608);
    else if (j < 32256) presplit_one(W3, dst + 13824,  64, 64,  j - 13824);
    else                presplit_one(W4, dst + 32256,  64, 128, j - 32256);
}
__global__ void presplit1x1_kernel(const float* __restrict__ W, uint2* __restrict__ dst)
{
    int i = blockIdx.x*256 + threadIdx.x;
    if (i >= 4096) return;
    int co = i & 63, pr = (i >> 6) & 7, q = i >> 9;
    int ci = q*16 + 2*pr;
    dst[i] = wpair(W[co*128 + ci], W[co*128 + ci + 1]);
}

// ---------------------------------------------------------------------------
// Activation transform + fused BN-stats finalization + next-sums zeroing.
// ---------------------------------------------------------------------------
template<bool BN, bool MASKED>
__global__ void transform_kernel(const float* __restrict__ y,
                                 const float* __restrict__ m,
                                 const float* __restrict__ sums,
                                 const float* __restrict__ gam,
                                 const float* __restrict__ bet,
                                 float* __restrict__ sums_next,
                                 uint32_t* __restrict__ out, int C, int n4)
{
    __shared__ float ssm[256];
    const int tid = threadIdx.x;
    if (BN) {
        if (tid < C) {
            const float invN = 1.f / (float)NPIX;
            float mean = sums[tid] * invN;
            float var  = sums[C + tid] * invN - mean*mean;
            float sc = gam[tid] * rsqrtf(var + 1e-5f);
            ssm[tid]     = sc;
            ssm[C + tid] = fmaf(-mean, sc, bet[tid]);
        }
        __syncthreads();
    }
    if (blockIdx.x == 0 && sums_next != nullptr && tid < 256) sums_next[tid] = 0.f;

    int i = blockIdx.x*256 + tid;
    if (i >= n4) return;
    int plane = i >> 14;
    int half = C >> 1;
    int pp = plane % half;
    int b  = plane / half;
    int c0 = pp*2;
    float sc0 = 1.f, sh0 = 0.f, sc1 = 1.f, sh1 = 0.f;
    if (BN) { sc0 = ssm[c0]; sh0 = ssm[C + c0]; sc1 = ssm[c0+1]; sh1 = ssm[C + c0 + 1]; }
    int px4 = i & 16383;
    float4 v0 = ((const float4*)y)[(((size_t)b*C + c0    ) << 14) + px4];
    float4 v1 = ((const float4*)y)[(((size_t)b*C + c0 + 1) << 14) + px4];
    float4 mk = make_float4(1.f,1.f,1.f,1.f);
    if (MASKED) mk = ((const float4*)m)[(((size_t)b) << 14) + px4];
    const float* p0 = &v0.x; const float* p1 = &v1.x; const float* pm = &mk.x;
    uint32_t r[4];
    #pragma unroll
    for (int k = 0; k < 4; k++) {
        float a = p0[k], c = p1[k];
        if (BN) {
            a = fmaf(a, sc0, sh0); a = a >= 0.f ? a : 0.01f*a;
            c = fmaf(c, sc1, sh1); c = c >= 0.f ? c : 0.01f*c;
        }
        if (MASKED) { a *= pm[k]; c *= pm[k]; }
        r[k] = pack2_f16(a, c);
    }
    ((uint4*)out)[i] = make_uint4(r[0], r[1], r[2], r[3]);
}

// ---------------------------------------------------------------------------
// Fused sparse-conv block, fp16 asymmetric-split MMA, NBUF-buffered 16B
// cp.async staging, conflict-free smem stride (3*WPX ≡ 8 mod 32).
// Inner loop: f-fragments processed in pairs with hi/hi/lo/lo ordering so
// dependent MMA pairs (same accumulator) have 2 independent MMAs between.
// ---------------------------------------------------------------------------
template<int CIN, int CO_BLK, int NSPLIT, int DIL, int PXT, int WARPS, int NBUF, int MINB>
__global__ void __launch_bounds__(WARPS*32, MINB) conv_mma_kernel(
    const uint32_t* __restrict__ xpk, const float* __restrict__ min_,
    const uint2* __restrict__ wsplit, const float* __restrict__ bg,
    float* __restrict__ yout, float* __restrict__ mout,
    float* __restrict__ sums)
{
    constexpr int NT    = WARPS*32;
    constexpr int PXG   = WARPS*16/CO_BLK;
    constexpr int XW    = PXT + 2*DIL;          // mask window (start x0-DIL)
    constexpr int WPX   = ((PXT + 8 - 24 + 31)/32)*32 + 24;
    constexpr int NCH   = (PXT + 8) / 4;        // 16B chunks per x row
    constexpr int XTSZ  = 24*WPX;
    constexpr int COUTT = CO_BLK*NSPLIT;
    constexpr int TX    = 256/PXT;
    constexpr int CHUNKS = CIN/16;
    constexpr int PLANES = CIN/2;

    extern __shared__ char dsm[];
    uint32_t* xt  = (uint32_t*)dsm;             // [NBUF][24][WPX], window start x0-4
    float*  msk = (float*)(xt + NBUF*XTSZ);     // [3][WPX]
    float*  invc= msk + 3*WPX;                  // [PXT]
    float*  red = invc + PXT;                   // [2*CO_BLK]

    const int tid  = threadIdx.x;
    const int lane = tid & 31, warp = tid >> 5;
    const int g    = lane >> 2, tig = lane & 3;
    const int cog  = warp / PXG, pxg = warp % PXG;
    const int pxb  = pxg * 64;
    const int cb   = cog * 16;
    const uint32_t sx = (uint32_t)__cvta_generic_to_shared(xt);

    const int tile = blockIdx.x;
    const int x0 = (tile % TX) * PXT;
    const int y0 = tile / TX;
    const int z  = blockIdx.z;
    const int b  = z / NSPLIT;
    const int split = z % NSPLIT;
    const int co_base = split * CO_BLK;

    // --- stage mask rows ---
    for (int i = tid; i < 3*XW; i += NT) {
        int col = i % XW, r = i / XW;
        int gy = y0 + (r-1)*DIL, gx = x0 - DIL + col;
        float v = 0.f;
        if (gy >= 0 && gy < Hh && gx >= 0 && gx < Ww) v = min_[b*HW + gy*Ww + gx];
        msk[r*WPX + col] = v;
    }
    for (int i = tid; i < 2*CO_BLK; i += NT) red[i] = 0.f;

    // 16B vector staging: chunk ch covers gx = x0-4+4ch .. +3 (all-or-nothing OOB)
    auto stage = [&](int q, int buf) {
        for (int pr = warp; pr < 8; pr += WARPS) {
            const uint32_t* srcp = xpk + (size_t)(b*PLANES + q*8 + pr)*HW;
            #pragma unroll
            for (int r = 0; r < 3; r++) {
                int gy = y0 + (r-1)*DIL;
                bool rowok = ((unsigned)gy < (unsigned)Hh);
                const uint32_t* srow = srcp + (rowok ? gy*Ww : 0);
                uint32_t dstb = sx + ((buf*XTSZ + (pr*3 + r)*WPX) << 2);
                #pragma unroll
                for (int ch = lane; ch < NCH; ch += 32) {
                    int gx = x0 - 4 + ch*4;
                    bool ok = rowok && (gx >= 0) && (gx < Ww);
                    cp_async16(dstb + (ch << 4), srow + (ok ? gx : 0), ok ? 16 : 0);
                }
            }
        }
        asm volatile("cp.async.commit_group;\n");
    };

    stage(0, 0);
    __syncthreads();

    // --- per-pixel 1/count + mask maxpool (overlaps chunk-0 arrival) ---
    for (int px = tid; px < PXT; px += NT) {
        float cnt = 0.f, mn = 0.f;
        #pragma unroll
        for (int ky = 0; ky < 3; ky++)
            #pragma unroll
            for (int kx = 0; kx < 3; kx++) {
                float v = msk[ky*WPX + px + kx*DIL];
                cnt += v; mn = fmaxf(mn, v);
            }
        invc[px] = 1.f / fmaxf(cnt * (float)CIN, 1e-5f);
        if (split == 0) mout[b*HW + y0*Ww + x0 + px] = mn;
    }

    float c[8][4];
    #pragma unroll
    for (int f = 0; f < 8; f++) { c[f][0]=0.f; c[f][1]=0.f; c[f][2]=0.f; c[f][3]=0.f; }

    for (int q = 0; q < CHUNKS; q++) {
        const int buf = (NBUF == 1) ? 0 : (q & 1);
        if (NBUF == 2 && q + 1 < CHUNKS) {
            stage(q + 1, buf ^ 1);
            asm volatile("cp.async.wait_group 1;\n");
        } else {
            asm volatile("cp.async.wait_group 0;\n");
        }
        __syncthreads();

        const uint32_t* xb = xt + buf*XTSZ;
        const uint2* Ab = wsplit + (size_t)(split*CHUNKS + q)*72*CO_BLK + cb + g;
        #pragma unroll 9
        for (int t = 0; t < 9; t++) {
            const int ky = t/3, kx = t - 3*ky;
            const int xoff = (kx-1)*DIL + 4;        // window-start shift
            const uint2* Ap = Ab + t*8*CO_BLK;
            uint2 A0 = __ldg(Ap + tig*CO_BLK);
            uint2 A1 = __ldg(Ap + tig*CO_BLK + 8);
            uint2 A2 = __ldg(Ap + (tig+4)*CO_BLK);
            uint2 A3 = __ldg(Ap + (tig+4)*CO_BLK + 8);
            const uint32_t* brow0 = &xb[(tig    *3 + ky)*WPX + pxb + xoff + g];
            const uint32_t* brow1 = &xb[((tig+4)*3 + ky)*WPX + pxb + xoff + g];
            // f-pair interleave: hi(f) hi(f+1) lo(f) lo(f+1); per-accumulator
            // order stays hi-then-lo per tap -> bit-identical results.
            #pragma unroll
            for (int f = 0; f < 8; f += 2) {
                uint32_t b0a = brow0[f*8];
                uint32_t b1a = brow1[f*8];
                uint32_t b0b = brow0[(f+1)*8];
                uint32_t b1b = brow1[(f+1)*8];
                mma16f(c[f],   A0.x, A1.x, A2.x, A3.x, b0a, b1a);  // hi f
                mma16f(c[f+1], A0.x, A1.x, A2.x, A3.x, b0b, b1b);  // hi f+1
                mma16f(c[f],   A0.y, A1.y, A2.y, A3.y, b0a, b1a);  // lo f
                mma16f(c[f+1], A0.y, A1.y, A2.y, A3.y, b0b, b1b);  // lo f+1
            }
        }
        if (q + 1 < CHUNKS) {
            __syncthreads();                        // all reads of buf done
            if (NBUF == 1) stage(q + 1, 0);         // restage in place
        }
    }

    // --- epilogue ---
    const int gco0 = co_base + cb + g;
    const int gco1 = gco0 + 8;
    const float b0v = bg[gco0], b1v = bg[gco1];
    float* rowp0 = yout + (size_t)(b*COUTT + gco0)*HW + y0*Ww + x0;
    float* rowp1 = yout + (size_t)(b*COUTT + gco1)*HW + y0*Ww + x0;
    float s0 = 0.f, q0 = 0.f, s1 = 0.f, q1 = 0.f;
    #pragma unroll
    for (int f = 0; f < 8; f++) {
        int pxl = pxb + f*8 + 2*tig;
        float i0 = invc[pxl], i1 = invc[pxl + 1];
        float y00 = fmaf(c[f][0], i0, b0v);
        float y01 = fmaf(c[f][1], i1, b0v);
        float y10 = fmaf(c[f][2], i0, b1v);
        float y11 = fmaf(c[f][3], i1, b1v);
        *(float2*)(rowp0 + pxl) = make_float2(y00, y01);
        *(float2*)(rowp1 + pxl) = make_float2(y10, y11);
        s0 += y00 + y01; q0 += y00*y00 + y01*y01;
        s1 += y10 + y11; q1 += y10*y10 + y11*y11;
    }
    #pragma unroll
    for (int o = 1; o <= 2; o <<= 1) {
        s0 += __shfl_xor_sync(0xffffffffu, s0, o);
        q0 += __shfl_xor_sync(0xffffffffu, q0, o);
        s1 += __shfl_xor_sync(0xffffffffu, s1, o);
        q1 += __shfl_xor_sync(0xffffffffu, q1, o);
    }
    if (tig == 0) {
        atomicAdd(&red[cb + g],              s0);
        atomicAdd(&red[CO_BLK + cb + g],     q0);
        atomicAdd(&red[cb + g + 8],          s1);
        atomicAdd(&red[CO_BLK + cb + g + 8], q1);
    }
    __syncthreads();
    if (tid < CO_BLK) {
        atomicAdd(&sums[co_base + tid],          red[tid]);
        atomicAdd(&sums[COUTT + co_base + tid],  red[CO_BLK + tid]);
    }
}

// ---------------------------------------------------------------------------
// final 1x1 conv 128 -> 64, fp16 asymmetric split, 16B double-buffered staging
// ---------------------------------------------------------------------------
__global__ void __launch_bounds__(256, 3) conv1x1_mma_kernel(
    const uint32_t* __restrict__ xpk, const uint2* __restrict__ wsp1,
    const float* __restrict__ bg, float* __restrict__ out)
{
    constexpr int CO = 64, PXT = 128, WPX1 = 140, PLANES = 64;
    __shared__ uint32_t xt[2*8*WPX1];

    const int tid = threadIdx.x, lane = tid & 31, warp = tid >> 5;
    const int g = lane >> 2, tig = lane & 3;
    const int cog = warp >> 1, pxg = warp & 1;
    const int pxb = pxg * 64;
    const int tile = blockIdx.x;
    const int x0 = (tile & 1)*PXT, y0 = tile >> 1;
    const int b  = blockIdx.z;
    const uint32_t sx = (uint32_t)__cvta_generic_to_shared(xt);

    auto stage = [&](int q, int buf) {
        const int pr = warp;
        const uint32_t* s = xpk + (size_t)(b*PLANES + q*8 + pr)*HW + y0*Ww + x0;
        uint32_t dstb = sx + ((buf*8*WPX1 + pr*WPX1) << 2);
        cp_async16(dstb + (lane << 4), s + lane*4, 16);
        asm volatile("cp.async.commit_group;\n");
    };

    float c[8][4];
    #pragma unroll
    for (int f = 0; f < 8; f++) { c[f][0]=0.f; c[f][1]=0.f; c[f][2]=0.f; c[f][3]=0.f; }

    stage(0, 0);
    for (int q = 0; q < 8; q++) {
        const int buf = q & 1;
        if (q + 1 < 8) {
            stage(q + 1, buf ^ 1);
            asm volatile("cp.async.wait_group 1;\n");
        } else {
            asm volatile("cp.async.wait_group 0;\n");
        }
        __syncthreads();

        const uint32_t* xb = xt + buf*8*WPX1;
        const uint2* Ap = wsp1 + q*512;
        uint2 a0 = __ldg(Ap + tig*64 + cog*16 + g);
        uint2 a1 = __ldg(Ap + tig*64 + cog*16 + g + 8);
        uint2 a2 = __ldg(Ap + (tig+4)*64 + cog*16 + g);
        uint2 a3 = __ldg(Ap + (tig+4)*64 + cog*16 + g + 8);
        #pragma unroll
        for (int f = 0; f < 8; f += 2) {
            uint32_t b0a = xb[tig    *WPX1 + pxb + f*8 + g];
            uint32_t b1a = xb[(tig+4)*WPX1 + pxb + f*8 + g];
            uint32_t b0b = xb[tig    *WPX1 + pxb + (f+1)*8 + g];
            uint32_t b1b = xb[(tig+4)*WPX1 + pxb + (f+1)*8 + g];
            mma16f(c[f],   a0.x, a1.x, a2.x, a3.x, b0a, b1a);
            mma16f(c[f+1], a0.x, a1.x, a2.x, a3.x, b0b, b1b);
            mma16f(c[f],   a0.y, a1.y, a2.y, a3.y, b0a, b1a);
            mma16f(c[f+1], a0.y, a1.y, a2.y, a3.y, b0b, b1b);
        }
        __syncthreads();
    }
    const int co0 = cog*16 + g, co1 = co0 + 8;
    const float b0v = bg[co0], b1v = bg[co1];
    float* r0 = out + (size_t)(b*CO + co0)*HW + y0*Ww + x0;
    float* r1 = out + (size_t)(b*CO + co1)*HW + y0*Ww + x0;
    #pragma unroll
    for (int f = 0; f < 8; f++) {
        int pxl = pxb + f*8 + 2*tig;
        *(float2*)(r0 + pxl) = make_float2(c[f][0] + b0v, c[f][1] + b0v);
        *(float2*)(r1 + pxl) = make_float2(c[f][2] + b1v, c[f][3] + b1v);
    }
}

// ---------------------------------------------------------------------------
extern "C" void kernel_launch(void* const* d_in, const int* in_sizes, int n_in,
                              void* d_out, int out_size)
{
    const float* feat = (const float*)d_in[0];
    const float* mask = (const float*)d_in[1];
    const float* Wl[5]; const float* bl[5]; const float* gl[5]; const float* bel[5];
    for (int l = 0; l < 5; l++) {
        Wl[l]  = (const float*)d_in[2 + 4*l];
        bl[l]  = (const float*)d_in[3 + 4*l];
        gl[l]  = (const float*)d_in[4 + 4*l];
        bel[l] = (const float*)d_in[5 + 4*l];
    }
    const float* Wf = (const float*)d_in[22];
    const float* bf = (const float*)d_in[23];

    float *bufA, *bufB, *mA, *mB, *sumsG;
    uint32_t* P;
    uint2* wsp;
    cudaGetSymbolAddress((void**)&bufA, g_bufA);
    cudaGetSymbolAddress((void**)&bufB, g_bufB);
    cudaGetSymbolAddress((void**)&P,    g_bufP);
    cudaGetSymbolAddress((void**)&mA,   g_maskA);
    cudaGetSymbolAddress((void**)&mB,   g_maskB);
    cudaGetSymbolAddress((void**)&sumsG, g_sums);
    cudaGetSymbolAddress((void**)&wsp,  g_wsplit);
    float* su0 = sumsG;
    float* su1 = sumsG + 256;

    const int off0 = 0, off1 = 2304, off2 = 4608, off3 = 13824, off4 = 32256;
    const int off1x1 = 69120;
    presplit3x3_all<<<270, 256>>>(Wl[0], Wl[1], Wl[2], Wl[3], Wl[4], wsp);
    presplit1x1_kernel<<<16, 256>>>(Wf, wsp+off1x1);

    // WPX: 256->280, 128->152, 64->88 ; L0/L1 single-buffered
    const int smem_L0 = 1*24*280*4 + 3*280*4 + 256*4 + 2*16*4 + 16;   // 31408
    const int smem_L1 = 1*24*280*4 + 3*280*4 + 256*4 + 2*32*4 + 16;   // 31536
    const int smem_Lx = 2*24*152*4 + 3*152*4 + 128*4 + 2*64*4 + 16;   // 32048
    const int smem_L4 = 2*24*88*4  + 3*88*4  + 64*4  + 2*128*4 + 16;  // 19248

    auto k0 = conv_mma_kernel<32,16,1,1,256,4,1,4>;
    auto k1 = conv_mma_kernel<16,32,1,2,256,8,1,3>;
    auto k2 = conv_mma_kernel<32,64,1,1,128,8,2,3>;
    auto k3 = conv_mma_kernel<64,64,1,2,128,8,2,3>;
    auto k4 = conv_mma_kernel<64,128,1,1,64,8,2,3>;
    cudaFuncSetAttribute(k0, cudaFuncAttributeMaxDynamicSharedMemorySize, smem_L0);
    cudaFuncSetAttribute(k1, cudaFuncAttributeMaxDynamicSharedMemorySize, smem_L1);
    cudaFuncSetAttribute(k2, cudaFuncAttributeMaxDynamicSharedMemorySize, smem_Lx);
    cudaFuncSetAttribute(k3, cudaFuncAttributeMaxDynamicSharedMemorySize, smem_Lx);
    cudaFuncSetAttribute(k4, cudaFuncAttributeMaxDynamicSharedMemorySize, smem_L4);

    auto TFM  = transform_kernel<true,  true >;
    auto TF0  = transform_kernel<false, true >;
    auto TFNM = transform_kernel<true,  false>;
    #define TGRID(C) ((C)*256)

    // input transform: feat*mask -> packed; zeroes su0 for L0
    TF0<<<TGRID(32), 256>>>(feat, mask, nullptr, nullptr, nullptr, su0, P, 32, 32*65536);

    // L0: 32 -> 16, d=1
    k0<<<dim3(256,1,8), 128, smem_L0>>>(P, mask, wsp+off0, bl[0], bufA, mA, su0);
    TFM<<<TGRID(16), 256>>>(bufA, mA, su0, gl[0], bel[0], su1, P, 16, 16*65536);

    // L1: 16 -> 32, d=2
    k1<<<dim3(256,1,8), 256, smem_L1>>>(P, mA, wsp+off1, bl[1], bufB, mB, su1);
    TFM<<<TGRID(32), 256>>>(bufB, mB, su1, gl[1], bel[1], su0, P, 32, 32*65536);

    // L2: 32 -> 64, d=1
    k2<<<dim3(512,1,8), 256, smem_Lx>>>(P, mB, wsp+off2, bl[2], bufA, mA, su0);
    TFM<<<TGRID(64), 256>>>(bufA, mA, su0, gl[2], bel[2], su1, P, 64, 64*65536);

    // L3: 64 -> 64, d=2
    k3<<<dim3(512,1,8), 256, smem_Lx>>>(P, mA, wsp+off3, bl[3], bufB, mB, su1);
    TFM<<<TGRID(64), 256>>>(bufB, mB, su1, gl[3], bel[3], su0, P, 64, 64*65536);

    // L4: 64 -> 128, d=1, single pass
    k4<<<dim3(1024,1,8), 256, smem_L4>>>(P, mB, wsp+off4, bl[4], bufA, mA, su0);
    TFNM<<<TGRID(128), 256>>>(bufA, nullptr, su0, gl[4], bel[4], nullptr, P, 128, 128*65536);

    // final 1x1 conv
    conv1x1_mma_kernel<<<dim3(512,1,8), 256>>>(P, wsp+off1x1, bf, (float*)d_out);

    // final mask
    const int xelems = Bb*64*HW;
    const int melems = Bb*HW;
    if (out_size >= xelems + melems) {
        cudaMemcpyAsync((float*)d_out + xelems, mA, (size_t)melems*sizeof(float),
                        cudaMemcpyDeviceToDevice);
    }
}